// round 5
// baseline (speedup 1.0000x reference)
#include <cuda_runtime.h>
#include <math.h>

// ---------------- problem constants ----------------
#define BSZ   32
#define NN    243
#define DD    544
#define HH    8
#define HDIM  68
#define NSD   17
#define UPD   1088          // UP*D
#define UCC   136           // UP*D/H
#define M1    2176          // 4*D
#define RR    (BSZ*NN)      // 7776
#define TD    (3*DD)        // 1632
#define BT    (2*NN-1)      // 485

// ---------------- scratch (device globals; no allocs allowed) ----------------
__device__ float g_x[RR*DD];
__device__ float g_h[RR*DD];
__device__ float g_qkv[RR*TD];
__device__ float g_o[RR*DD];
__device__ float g_big[RR*M1];          // reused: mlp hidden | xu + o2 | emlp hidden
__device__ float g_a[BSZ*HH*NN*NSD];
__device__ float g_s0[NSD*UPD];
__device__ float g_s1[NSD*UPD];
__device__ float g_mean[NSD];

__device__ __forceinline__ float gelu_exact(float v) {
    return 0.5f * v * (1.0f + erff(v * 0.70710678118654752f));
}

// ---------------- generic copy ----------------
__global__ void copy_kernel(const float* __restrict__ in, float* __restrict__ out, int n) {
    int i = blockIdx.x * blockDim.x + threadIdx.x;
    if (i < n) out[i] = in[i];
}

// ---------------- layernorm: one block per row, D=544 ----------------
__global__ void ln_kernel(const float* __restrict__ in, float* __restrict__ out,
                          const float* __restrict__ g, const float* __restrict__ b) {
    int row = blockIdx.x;
    const float* xr = in + (size_t)row * DD;
    __shared__ float red[256];
    int tid = threadIdx.x;

    float s = 0.f;
    for (int i = tid; i < DD; i += 256) s += xr[i];
    red[tid] = s; __syncthreads();
    for (int off = 128; off; off >>= 1) { if (tid < off) red[tid] += red[tid + off]; __syncthreads(); }
    float mean = red[0] * (1.0f / DD);
    __syncthreads();

    float s2 = 0.f;
    for (int i = tid; i < DD; i += 256) { float d = xr[i] - mean; s2 += d * d; }
    red[tid] = s2; __syncthreads();
    for (int off = 128; off; off >>= 1) { if (tid < off) red[tid] += red[tid + off]; __syncthreads(); }
    float rs = rsqrtf(red[0] * (1.0f / DD) + 1e-5f);

    for (int i = tid; i < DD; i += 256)
        out[(size_t)row * DD + i] = (xr[i] - mean) * rs * g[i] + b[i];
}

// ---------------- NT GEMM: C[M,Nc] = A[M,K] @ B[Nc,K]^T (+bias)(epilogue) ----------
// EPI: 0 = store, 1 = accumulate into C (residual), 2 = gelu store
template <int EPI>
__global__ void gemm_nt(const float* __restrict__ A, const float* __restrict__ B,
                        const float* __restrict__ bias, float* __restrict__ C,
                        int M, int Nc, int K) {
    __shared__ float As[64][17];
    __shared__ float Bs[16][68];
    int tid = threadIdx.x;
    int tx = tid & 15, ty = tid >> 4;
    int row0 = blockIdx.y * 64, col0 = blockIdx.x * 64;
    int lr = tid >> 2;            // 0..63
    int lc = (tid & 3) * 4;       // 0,4,8,12

    float acc[4][4];
    #pragma unroll
    for (int i = 0; i < 4; i++)
        #pragma unroll
        for (int j = 0; j < 4; j++) acc[i][j] = 0.f;

    for (int k0 = 0; k0 < K; k0 += 16) {
        // load A tile (row-major, K contiguous, K % 16 == 0)
        {
            int r = row0 + lr;
            float4 v = make_float4(0.f, 0.f, 0.f, 0.f);
            if (r < M) v = *reinterpret_cast<const float4*>(A + (size_t)r * K + k0 + lc);
            As[lr][lc + 0] = v.x; As[lr][lc + 1] = v.y; As[lr][lc + 2] = v.z; As[lr][lc + 3] = v.w;
        }
        // load B tile transposed into Bs[k][n]
        {
            int n = col0 + lr;
            float4 v = make_float4(0.f, 0.f, 0.f, 0.f);
            if (n < Nc) v = *reinterpret_cast<const float4*>(B + (size_t)n * K + k0 + lc);
            Bs[lc + 0][lr] = v.x; Bs[lc + 1][lr] = v.y; Bs[lc + 2][lr] = v.z; Bs[lc + 3][lr] = v.w;
        }
        __syncthreads();
        #pragma unroll
        for (int k = 0; k < 16; ++k) {
            float a[4], bb[4];
            #pragma unroll
            for (int i = 0; i < 4; i++) a[i] = As[ty * 4 + i][k];
            #pragma unroll
            for (int j = 0; j < 4; j++) bb[j] = Bs[k][tx * 4 + j];
            #pragma unroll
            for (int i = 0; i < 4; i++)
                #pragma unroll
                for (int j = 0; j < 4; j++) acc[i][j] = fmaf(a[i], bb[j], acc[i][j]);
        }
        __syncthreads();
    }

    #pragma unroll
    for (int i = 0; i < 4; i++) {
        int r = row0 + ty * 4 + i;
        if (r >= M) continue;
        #pragma unroll
        for (int j = 0; j < 4; j++) {
            int c = col0 + tx * 4 + j;
            if (c >= Nc) continue;
            float v = acc[i][j];
            if (bias) v += bias[c];
            size_t idx = (size_t)r * Nc + c;
            if (EPI == 1)      C[idx] += v;
            else if (EPI == 2) C[idx] = gelu_exact(v);
            else               C[idx] = v;
        }
    }
}

// ---------------- fused attention: one block per (b,h); K,V resident in SMEM ----
// smem floats: K 243*69, V 243*69, S 243, red 256, O 3*68, Q 68
#define ATTN_SMEM_FLOATS (2*NN*69 + NN + 256 + 3*HDIM + HDIM)
__global__ void attn_fused(const float* __restrict__ qkv, const float* __restrict__ btab,
                           float* __restrict__ o) {
    extern __shared__ float sm[];
    float* sK  = sm;
    float* sV  = sK + NN * 69;
    float* sS  = sV + NN * 69;
    float* red = sS + NN;
    float* sO  = red + 256;
    float* sQ  = sO + 3 * HDIM;

    int b = blockIdx.x / HH, h = blockIdx.x % HH;
    int tid = threadIdx.x;
    const float* base = qkv + (size_t)b * NN * TD + h * HDIM;

    for (int idx = tid; idx < NN * HDIM; idx += 256) {
        int j = idx / HDIM, d = idx - j * HDIM;
        sK[j * 69 + d] = base[(size_t)j * TD + DD + d];
        sV[j * 69 + d] = base[(size_t)j * TD + 2 * DD + d];
    }
    const float scale = rsqrtf((float)HDIM);
    const float* bt = btab + h * BT;

    for (int i = 0; i < NN; ++i) {
        __syncthreads();
        if (tid < HDIM) sQ[tid] = base[(size_t)i * TD + tid];
        __syncthreads();

        float lmax = -1e30f;
        if (tid < NN) {
            float s = 0.f;
            #pragma unroll 4
            for (int d = 0; d < HDIM; ++d) s = fmaf(sQ[d], sK[tid * 69 + d], s);
            s = s * scale + bt[i - tid + NN - 1];
            sS[tid] = s;
            lmax = s;
        }
        red[tid] = lmax; __syncthreads();
        for (int off = 128; off; off >>= 1) { if (tid < off) red[tid] = fmaxf(red[tid], red[tid + off]); __syncthreads(); }
        float mx = red[0]; __syncthreads();

        float e = 0.f;
        if (tid < NN) { e = __expf(sS[tid] - mx); sS[tid] = e; }
        red[tid] = e; __syncthreads();
        for (int off = 128; off; off >>= 1) { if (tid < off) red[tid] += red[tid + off]; __syncthreads(); }
        float inv = 1.f / red[0];
        __syncthreads();

        int chunk = tid / HDIM;
        if (chunk < 3) {
            int d = tid - chunk * HDIM;
            int j0 = chunk * 81, j1 = j0 + 81;
            if (j1 > NN) j1 = NN;
            float acc = 0.f;
            for (int j = j0; j < j1; ++j) acc = fmaf(sS[j], sV[j * 69 + d], acc);
            sO[chunk * HDIM + d] = acc;
        }
        __syncthreads();
        if (tid < HDIM)
            o[(size_t)(b * NN + i) * DD + h * HDIM + tid] =
                (sO[tid] + sO[HDIM + tid] + sO[2 * HDIM + tid]) * inv;
    }
}

// ---------------- seed attention ----------------
// a[b,h,f,n] = sum_c xu[b,f,h*UC+c] * s0[n, h*UC+c]
__global__ void seed_scores(const float* __restrict__ xu, const float* __restrict__ s0,
                            float* __restrict__ a) {
    int bid = blockIdx.x;
    int f = bid % NN;
    int t = bid / NN;
    int h = t % HH, b = t / HH;
    __shared__ float sx[UCC];
    const float* xr = xu + (size_t)(b * NN + f) * UPD + h * UCC;
    for (int i = threadIdx.x; i < UCC; i += blockDim.x) sx[i] = xr[i];
    __syncthreads();
    if (threadIdx.x < NSD) {
        const float* sr = s0 + (size_t)threadIdx.x * UPD + h * UCC;
        float acc = 0.f;
        #pragma unroll 4
        for (int c = 0; c < UCC; ++c) acc = fmaf(sx[c], sr[c], acc);
        a[((size_t)(b * HH + h) * NN + f) * NSD + threadIdx.x] = acc;
    }
}

// softmax over f (243) for each (b,h,n)
__global__ void softmax_f(float* __restrict__ a) {
    int bid = blockIdx.x;
    int n = bid % NSD, bh = bid / NSD;
    __shared__ float red[256];
    int f = threadIdx.x;
    size_t base = (size_t)bh * NN * NSD + n;
    float v = (f < NN) ? a[base + (size_t)f * NSD] : -1e30f;
    red[f] = v; __syncthreads();
    for (int off = 128; off; off >>= 1) { if (f < off) red[f] = fmaxf(red[f], red[f + off]); __syncthreads(); }
    float mx = red[0]; __syncthreads();
    float e = (f < NN) ? __expf(v - mx) : 0.f;
    red[f] = e; __syncthreads();
    for (int off = 128; off; off >>= 1) { if (f < off) red[f] += red[f + off]; __syncthreads(); }
    float inv = 1.f / red[0];
    if (f < NN) a[base + (size_t)f * NSD] = e * inv;
}

__global__ void zero_mean(float* __restrict__ mean) {
    if (threadIdx.x < NSD) mean[threadIdx.x] = 0.f;
}

// per (b,h,f): divide by (1e-7 + sum_n), accumulate per-n sums for mean_attn
__global__ void norm_n_mean(float* __restrict__ a, float* __restrict__ mean) {
    int bh = blockIdx.x;  // 0..255
    __shared__ float sacc[NSD];
    if (threadIdx.x < NSD) sacc[threadIdx.x] = 0.f;
    __syncthreads();
    for (int f = threadIdx.x; f < NN; f += blockDim.x) {
        float* row = a + ((size_t)bh * NN + f) * NSD;
        float vals[NSD];
        float s = 0.f;
        #pragma unroll
        for (int n = 0; n < NSD; ++n) { vals[n] = row[n]; s += vals[n]; }
        float inv = 1.f / (1e-7f + s);
        #pragma unroll
        for (int n = 0; n < NSD; ++n) {
            float nv = vals[n] * inv;
            row[n] = nv;
            atomicAdd(&sacc[n], nv);
        }
    }
    __syncthreads();
    if (threadIdx.x < NSD) atomicAdd(&mean[threadIdx.x], sacc[threadIdx.x]);
}

// o2[b,f,h*UC+c] = sum_n a[b,h,f,n] * s1[n, h*UC+c]
__global__ void seed_out(const float* __restrict__ a, const float* __restrict__ s1,
                         float* __restrict__ o2) {
    int idx = blockIdx.x * blockDim.x + threadIdx.x;
    if (idx >= RR * UPD) return;
    int r = idx / UPD, c = idx - r * UPD;
    int b = r / NN, f = r - b * NN;
    int h = c / UCC;
    const float* ar = a + ((size_t)(b * HH + h) * NN + f) * NSD;
    float acc = 0.f;
    #pragma unroll
    for (int n = 0; n < NSD; ++n) acc = fmaf(ar[n], s1[(size_t)n * UPD + c], acc);
    o2[idx] = acc;
}

__global__ void finalize_mean(const float* __restrict__ mean, float* __restrict__ out) {
    if (threadIdx.x < NSD)
        out[(size_t)RR * DD + threadIdx.x] = mean[threadIdx.x] * (1.0f / (BSZ * HH * NN));
}

// ---------------- launch ----------------
extern "C" void kernel_launch(void* const* d_in, const int* in_sizes, int n_in,
                              void* d_out, int out_size) {
    (void)in_sizes; (void)n_in; (void)out_size;
    const float* x       = (const float*)d_in[0];
    const float* seed    = (const float*)d_in[1];
    const float* ln1_g   = (const float*)d_in[2];
    const float* ln1_b   = (const float*)d_in[3];
    const float* w_qkv   = (const float*)d_in[4];
    const float* w_proj  = (const float*)d_in[5];
    const float* b_proj  = (const float*)d_in[6];
    const float* b_table = (const float*)d_in[7];
    const float* ln2_g   = (const float*)d_in[8];
    const float* ln2_b   = (const float*)d_in[9];
    const float* mlp_w1  = (const float*)d_in[10];
    const float* mlp_b1  = (const float*)d_in[11];
    const float* mlp_w2  = (const float*)d_in[12];
    const float* mlp_b2  = (const float*)d_in[13];
    const float* eln1_g  = (const float*)d_in[14];
    const float* eln1_b  = (const float*)d_in[15];
    const float* w_trans = (const float*)d_in[16];
    const float* b_trans = (const float*)d_in[17];
    const float* w0      = (const float*)d_in[18];
    const float* b0      = (const float*)d_in[19];
    const float* w1      = (const float*)d_in[20];
    const float* b1      = (const float*)d_in[21];
    const float* w_proj2 = (const float*)d_in[22];
    const float* b_proj2 = (const float*)d_in[23];
    const float* eln2_g  = (const float*)d_in[24];
    const float* eln2_b  = (const float*)d_in[25];
    const float* emlp_w1 = (const float*)d_in[26];
    const float* emlp_b1 = (const float*)d_in[27];
    const float* emlp_w2 = (const float*)d_in[28];
    const float* emlp_b2 = (const float*)d_in[29];
    float* out = (float*)d_out;

    float *px, *ph, *pqkv, *po, *pbig, *pa, *ps0, *ps1, *pmean;
    cudaGetSymbolAddress((void**)&px,    g_x);
    cudaGetSymbolAddress((void**)&ph,    g_h);
    cudaGetSymbolAddress((void**)&pqkv,  g_qkv);
    cudaGetSymbolAddress((void**)&po,    g_o);
    cudaGetSymbolAddress((void**)&pbig,  g_big);
    cudaGetSymbolAddress((void**)&pa,    g_a);
    cudaGetSymbolAddress((void**)&ps0,   g_s0);
    cudaGetSymbolAddress((void**)&ps1,   g_s1);
    cudaGetSymbolAddress((void**)&pmean, g_mean);

    const int attn_smem = ATTN_SMEM_FLOATS * (int)sizeof(float);
    cudaFuncSetAttribute(attn_fused, cudaFuncAttributeMaxDynamicSharedMemorySize, attn_smem);

    dim3 blk(256);
    const int MB = (RR + 63) / 64;   // 122

    // x -> g_x (running residual stream)
    copy_kernel<<<(RR * DD + 255) / 256, blk>>>(x, px, RR * DD);

    // --- block 1: attention ---
    ln_kernel<<<RR, blk>>>(px, ph, ln1_g, ln1_b);
    gemm_nt<0><<<dim3((TD + 63) / 64, MB), blk>>>(ph, w_qkv, nullptr, pqkv, RR, TD, DD);
    attn_fused<<<BSZ * HH, blk, attn_smem>>>(pqkv, b_table, po);
    gemm_nt<1><<<dim3((DD + 63) / 64, MB), blk>>>(po, w_proj, b_proj, px, RR, DD, DD);

    // --- block 2: MLP ---
    ln_kernel<<<RR, blk>>>(px, ph, ln2_g, ln2_b);
    gemm_nt<2><<<dim3((M1 + 63) / 64, MB), blk>>>(ph, mlp_w1, mlp_b1, pbig, RR, M1, DD);
    gemm_nt<1><<<dim3((DD + 63) / 64, MB), blk>>>(pbig, mlp_w2, mlp_b2, px, RR, DD, M1);

    // --- block 3: seed attention ---
    ln_kernel<<<RR, blk>>>(px, ph, eln1_g, eln1_b);
    float* pxu = pbig;                       // RR x UPD
    float* po2 = pbig + (size_t)RR * UPD;    // RR x UPD
    gemm_nt<0><<<dim3((UPD + 63) / 64, MB), blk>>>(ph, w_trans, b_trans, pxu, RR, UPD, DD);
    gemm_nt<0><<<dim3((UPD + 63) / 64, 1), blk>>>(seed, w0, b0, ps0, NSD, UPD, DD);
    gemm_nt<0><<<dim3((UPD + 63) / 64, 1), blk>>>(seed, w1, b1, ps1, NSD, UPD, DD);
    seed_scores<<<BSZ * HH * NN, dim3(128)>>>(pxu, ps0, pa);
    softmax_f<<<BSZ * HH * NSD, blk>>>(pa);
    zero_mean<<<1, 32>>>(pmean);
    norm_n_mean<<<BSZ * HH, blk>>>(pa, pmean);
    seed_out<<<(RR * UPD + 255) / 256, blk>>>(pa, ps1, po2);
    gemm_nt<1><<<dim3((DD + 63) / 64, MB), blk>>>(po2, w_proj2, b_proj2, px, RR, DD, UPD);

    // --- block 4: expansion MLP ---
    ln_kernel<<<RR, blk>>>(px, ph, eln2_g, eln2_b);
    gemm_nt<2><<<dim3((UPD + 63) / 64, MB), blk>>>(ph, emlp_w1, emlp_b1, pbig, RR, UPD, DD);
    gemm_nt<1><<<dim3((DD + 63) / 64, MB), blk>>>(pbig, emlp_w2, emlp_b2, px, RR, DD, UPD);

    // --- output ---
    copy_kernel<<<(RR * DD + 255) / 256, blk>>>(px, out, RR * DD);
    finalize_mean<<<1, 32>>>(pmean, out);
}

// round 8
// speedup vs baseline: 2.4982x; 2.4982x over previous
#include <cuda_runtime.h>
#include <math.h>

// ---------------- problem constants ----------------
#define BSZ   32
#define NN    243
#define DD    544
#define HH    8
#define HDIM  68
#define NSD   17
#define UPD   1088          // UP*D
#define UCC   136           // UP*D/H
#define M1    2176          // 4*D
#define RR    (BSZ*NN)      // 7776
#define TD    (3*DD)        // 1632
#define BT    (2*NN-1)      // 485

// ---------------- scratch (device globals; no allocs allowed) ----------------
__device__ float g_x[RR*DD];
__device__ float g_h[RR*DD];
__device__ float g_qkv[RR*TD];
__device__ float g_o[RR*DD];
__device__ float g_big[RR*M1];          // reused: mlp hidden | xu + o2 | emlp hidden
__device__ float g_a[BSZ*HH*NN*NSD];
__device__ float g_s0[NSD*UPD];
__device__ float g_s1[NSD*UPD];
__device__ float g_mean[NSD];

__device__ __forceinline__ float gelu_exact(float v) {
    return 0.5f * v * (1.0f + erff(v * 0.70710678118654752f));
}

__device__ __forceinline__ float to_tf32(float x) {
    unsigned r;
    asm("cvt.rna.tf32.f32 %0, %1;" : "=r"(r) : "f"(x));
    return __uint_as_float(r);
}

__device__ __forceinline__ void mma_tf32(float* c, const float* a, const float* b) {
    asm volatile(
        "mma.sync.aligned.m16n8k8.row.col.f32.tf32.tf32.f32 "
        "{%0,%1,%2,%3},{%4,%5,%6,%7},{%8,%9},{%0,%1,%2,%3};"
        : "+f"(c[0]), "+f"(c[1]), "+f"(c[2]), "+f"(c[3])
        : "r"(__float_as_uint(a[0])), "r"(__float_as_uint(a[1])),
          "r"(__float_as_uint(a[2])), "r"(__float_as_uint(a[3])),
          "r"(__float_as_uint(b[0])), "r"(__float_as_uint(b[1])));
}

// ---------------- generic copy ----------------
__global__ void copy_kernel(const float* __restrict__ in, float* __restrict__ out, int n) {
    int i = blockIdx.x * blockDim.x + threadIdx.x;
    if (i < n) out[i] = in[i];
}

// ---------------- layernorm: one block per row, D=544 ----------------
__global__ void ln_kernel(const float* __restrict__ in, float* __restrict__ out,
                          const float* __restrict__ g, const float* __restrict__ b) {
    int row = blockIdx.x;
    const float* xr = in + (size_t)row * DD;
    __shared__ float red[256];
    int tid = threadIdx.x;

    float s = 0.f;
    for (int i = tid; i < DD; i += 256) s += xr[i];
    red[tid] = s; __syncthreads();
    for (int off = 128; off; off >>= 1) { if (tid < off) red[tid] += red[tid + off]; __syncthreads(); }
    float mean = red[0] * (1.0f / DD);
    __syncthreads();

    float s2 = 0.f;
    for (int i = tid; i < DD; i += 256) { float d = xr[i] - mean; s2 += d * d; }
    red[tid] = s2; __syncthreads();
    for (int off = 128; off; off >>= 1) { if (tid < off) red[tid] += red[tid + off]; __syncthreads(); }
    float rs = rsqrtf(red[0] * (1.0f / DD) + 1e-5f);

    for (int i = tid; i < DD; i += 256)
        out[(size_t)row * DD + i] = (xr[i] - mean) * rs * g[i] + b[i];
}

// ---------------- tf32 tensor-core NT GEMM ----------------
// C[M,Nc] = A[M,K] @ B[Nc,K]^T (+bias)(epilogue)
// EPI: 0 = store, 1 = accumulate into C (residual), 2 = gelu store
// CTA tile 128x64, BK=16, 8 warps in 4(M) x 2(N); warp tile 32x32 = 2x4 m16n8k8.
// Requires: K % 16 == 0. M and Nc fully guarded.
#define PAD 20
template <int EPI>
__global__ __launch_bounds__(256)
void gemm_mma(const float* __restrict__ A, const float* __restrict__ B,
              const float* __restrict__ bias, float* __restrict__ C,
              int M, int Nc, int K) {
    __shared__ float As[128][PAD];
    __shared__ float Bs[64][PAD];

    int tid  = threadIdx.x;
    int lane = tid & 31;
    int warp = tid >> 5;
    int wm   = warp & 3;       // 0..3 -> 32-row slab
    int wn   = warp >> 2;      // 0..1 -> 32-col slab

    int row0 = blockIdx.y * 128;
    int col0 = blockIdx.x * 64;

    int g = lane >> 2;         // 0..7
    int t = lane & 3;          // 0..3

    // global load indexing
    int lr = tid >> 2;         // 0..63
    int lc = (tid & 3) * 4;    // 0,4,8,12

    float acc[2][4][4];
    #pragma unroll
    for (int mi = 0; mi < 2; mi++)
        #pragma unroll
        for (int ni = 0; ni < 4; ni++)
            #pragma unroll
            for (int q = 0; q < 4; q++) acc[mi][ni][q] = 0.f;

    for (int k0 = 0; k0 < K; k0 += 16) {
        // A tile: 128x16, two rows per thread
        #pragma unroll
        for (int half = 0; half < 2; half++) {
            int r = lr + half * 64;
            int gr = row0 + r;
            float4 v = make_float4(0.f, 0.f, 0.f, 0.f);
            if (gr < M) v = *reinterpret_cast<const float4*>(A + (size_t)gr * K + k0 + lc);
            As[r][lc + 0] = to_tf32(v.x);
            As[r][lc + 1] = to_tf32(v.y);
            As[r][lc + 2] = to_tf32(v.z);
            As[r][lc + 3] = to_tf32(v.w);
        }
        // B tile: 64x16, guarded (Nc may not be a multiple of 64)
        {
            int n = col0 + lr;
            float4 v = make_float4(0.f, 0.f, 0.f, 0.f);
            if (n < Nc) v = *reinterpret_cast<const float4*>(B + (size_t)n * K + k0 + lc);
            Bs[lr][lc + 0] = to_tf32(v.x);
            Bs[lr][lc + 1] = to_tf32(v.y);
            Bs[lr][lc + 2] = to_tf32(v.z);
            Bs[lr][lc + 3] = to_tf32(v.w);
        }
        __syncthreads();

        #pragma unroll
        for (int kk = 0; kk < 16; kk += 8) {
            float afr[2][4];
            #pragma unroll
            for (int mi = 0; mi < 2; mi++) {
                int mb = wm * 32 + mi * 16;
                afr[mi][0] = As[mb + g     ][kk + t    ];
                afr[mi][1] = As[mb + g + 8 ][kk + t    ];
                afr[mi][2] = As[mb + g     ][kk + t + 4];
                afr[mi][3] = As[mb + g + 8 ][kk + t + 4];
            }
            float bfr[4][2];
            #pragma unroll
            for (int ni = 0; ni < 4; ni++) {
                int nb = wn * 32 + ni * 8;
                bfr[ni][0] = Bs[nb + g][kk + t    ];
                bfr[ni][1] = Bs[nb + g][kk + t + 4];
            }
            #pragma unroll
            for (int mi = 0; mi < 2; mi++)
                #pragma unroll
                for (int ni = 0; ni < 4; ni++)
                    mma_tf32(acc[mi][ni], afr[mi], bfr[ni]);
        }
        __syncthreads();
    }

    // epilogue: c0:(g,2t) c1:(g,2t+1) c2:(g+8,2t) c3:(g+8,2t+1)
    #pragma unroll
    for (int mi = 0; mi < 2; mi++) {
        #pragma unroll
        for (int rh = 0; rh < 2; rh++) {
            int r = row0 + wm * 32 + mi * 16 + g + rh * 8;
            if (r >= M) continue;
            #pragma unroll
            for (int ni = 0; ni < 4; ni++) {
                int c = col0 + wn * 32 + ni * 8 + t * 2;
                if (c >= Nc) continue;   // Nc even, c even -> c+1 < Nc too
                #pragma unroll
                for (int cc = 0; cc < 2; cc++) {
                    float v = acc[mi][ni][rh * 2 + cc];
                    if (bias) v += bias[c + cc];
                    size_t idx = (size_t)r * Nc + c + cc;
                    if (EPI == 1)      C[idx] += v;
                    else if (EPI == 2) C[idx] = gelu_exact(v);
                    else               C[idx] = v;
                }
            }
        }
    }
}

// ---------------- fused attention: one block per (b,h); K,V resident in SMEM ----
#define ATTN_SMEM_FLOATS (2*NN*69 + NN + 256 + 3*HDIM + HDIM)
__global__ void attn_fused(const float* __restrict__ qkv, const float* __restrict__ btab,
                           float* __restrict__ o) {
    extern __shared__ float sm[];
    float* sK  = sm;
    float* sV  = sK + NN * 69;
    float* sS  = sV + NN * 69;
    float* red = sS + NN;
    float* sO  = red + 256;
    float* sQ  = sO + 3 * HDIM;

    int b = blockIdx.x / HH, h = blockIdx.x % HH;
    int tid = threadIdx.x;
    const float* base = qkv + (size_t)b * NN * TD + h * HDIM;

    for (int idx = tid; idx < NN * HDIM; idx += 256) {
        int j = idx / HDIM, d = idx - j * HDIM;
        sK[j * 69 + d] = base[(size_t)j * TD + DD + d];
        sV[j * 69 + d] = base[(size_t)j * TD + 2 * DD + d];
    }
    const float scale = rsqrtf((float)HDIM);
    const float* bt = btab + h * BT;

    for (int i = 0; i < NN; ++i) {
        __syncthreads();
        if (tid < HDIM) sQ[tid] = base[(size_t)i * TD + tid];
        __syncthreads();

        float lmax = -1e30f;
        if (tid < NN) {
            float s = 0.f;
            #pragma unroll 4
            for (int d = 0; d < HDIM; ++d) s = fmaf(sQ[d], sK[tid * 69 + d], s);
            s = s * scale + bt[i - tid + NN - 1];
            sS[tid] = s;
            lmax = s;
        }
        red[tid] = lmax; __syncthreads();
        for (int off = 128; off; off >>= 1) { if (tid < off) red[tid] = fmaxf(red[tid], red[tid + off]); __syncthreads(); }
        float mx = red[0]; __syncthreads();

        float e = 0.f;
        if (tid < NN) { e = __expf(sS[tid] - mx); sS[tid] = e; }
        red[tid] = e; __syncthreads();
        for (int off = 128; off; off >>= 1) { if (tid < off) red[tid] += red[tid + off]; __syncthreads(); }
        float inv = 1.f / red[0];
        __syncthreads();

        int chunk = tid / HDIM;
        if (chunk < 3) {
            int d = tid - chunk * HDIM;
            int j0 = chunk * 81, j1 = j0 + 81;
            if (j1 > NN) j1 = NN;
            float acc = 0.f;
            for (int j = j0; j < j1; ++j) acc = fmaf(sS[j], sV[j * 69 + d], acc);
            sO[chunk * HDIM + d] = acc;
        }
        __syncthreads();
        if (tid < HDIM)
            o[(size_t)(b * NN + i) * DD + h * HDIM + tid] =
                (sO[tid] + sO[HDIM + tid] + sO[2 * HDIM + tid]) * inv;
    }
}

// ---------------- seed attention ----------------
__global__ void seed_scores(const float* __restrict__ xu, const float* __restrict__ s0,
                            float* __restrict__ a) {
    int bid = blockIdx.x;
    int f = bid % NN;
    int t = bid / NN;
    int h = t % HH, b = t / HH;
    __shared__ float sx[UCC];
    const float* xr = xu + (size_t)(b * NN + f) * UPD + h * UCC;
    for (int i = threadIdx.x; i < UCC; i += blockDim.x) sx[i] = xr[i];
    __syncthreads();
    if (threadIdx.x < NSD) {
        const float* sr = s0 + (size_t)threadIdx.x * UPD + h * UCC;
        float acc = 0.f;
        #pragma unroll 4
        for (int c = 0; c < UCC; ++c) acc = fmaf(sx[c], sr[c], acc);
        a[((size_t)(b * HH + h) * NN + f) * NSD + threadIdx.x] = acc;
    }
}

__global__ void softmax_f(float* __restrict__ a) {
    int bid = blockIdx.x;
    int n = bid % NSD, bh = bid / NSD;
    __shared__ float red[256];
    int f = threadIdx.x;
    size_t base = (size_t)bh * NN * NSD + n;
    float v = (f < NN) ? a[base + (size_t)f * NSD] : -1e30f;
    red[f] = v; __syncthreads();
    for (int off = 128; off; off >>= 1) { if (f < off) red[f] = fmaxf(red[f], red[f + off]); __syncthreads(); }
    float mx = red[0]; __syncthreads();
    float e = (f < NN) ? __expf(v - mx) : 0.f;
    red[f] = e; __syncthreads();
    for (int off = 128; off; off >>= 1) { if (f < off) red[f] += red[f + off]; __syncthreads(); }
    float inv = 1.f / red[0];
    if (f < NN) a[base + (size_t)f * NSD] = e * inv;
}

__global__ void zero_mean(float* __restrict__ mean) {
    if (threadIdx.x < NSD) mean[threadIdx.x] = 0.f;
}

__global__ void norm_n_mean(float* __restrict__ a, float* __restrict__ mean) {
    int bh = blockIdx.x;  // 0..255
    __shared__ float sacc[NSD];
    if (threadIdx.x < NSD) sacc[threadIdx.x] = 0.f;
    __syncthreads();
    for (int f = threadIdx.x; f < NN; f += blockDim.x) {
        float* row = a + ((size_t)bh * NN + f) * NSD;
        float vals[NSD];
        float s = 0.f;
        #pragma unroll
        for (int n = 0; n < NSD; ++n) { vals[n] = row[n]; s += vals[n]; }
        float inv = 1.f / (1e-7f + s);
        #pragma unroll
        for (int n = 0; n < NSD; ++n) {
            float nv = vals[n] * inv;
            row[n] = nv;
            atomicAdd(&sacc[n], nv);
        }
    }
    __syncthreads();
    if (threadIdx.x < NSD) atomicAdd(&mean[threadIdx.x], sacc[threadIdx.x]);
}

__global__ void seed_out(const float* __restrict__ a, const float* __restrict__ s1,
                         float* __restrict__ o2) {
    int idx = blockIdx.x * blockDim.x + threadIdx.x;
    if (idx >= RR * UPD) return;
    int r = idx / UPD, c = idx - r * UPD;
    int b = r / NN, f = r - b * NN;
    int h = c / UCC;
    const float* ar = a + ((size_t)(b * HH + h) * NN + f) * NSD;
    float acc = 0.f;
    #pragma unroll
    for (int n = 0; n < NSD; ++n) acc = fmaf(ar[n], s1[(size_t)n * UPD + c], acc);
    o2[idx] = acc;
}

__global__ void finalize_mean(const float* __restrict__ mean, float* __restrict__ out) {
    if (threadIdx.x < NSD)
        out[(size_t)RR * DD + threadIdx.x] = mean[threadIdx.x] * (1.0f / (BSZ * HH * NN));
}

// ---------------- launch ----------------
extern "C" void kernel_launch(void* const* d_in, const int* in_sizes, int n_in,
                              void* d_out, int out_size) {
    (void)in_sizes; (void)n_in; (void)out_size;
    const float* x       = (const float*)d_in[0];
    const float* seed    = (const float*)d_in[1];
    const float* ln1_g   = (const float*)d_in[2];
    const float* ln1_b   = (const float*)d_in[3];
    const float* w_qkv   = (const float*)d_in[4];
    const float* w_proj  = (const float*)d_in[5];
    const float* b_proj  = (const float*)d_in[6];
    const float* b_table = (const float*)d_in[7];
    const float* ln2_g   = (const float*)d_in[8];
    const float* ln2_b   = (const float*)d_in[9];
    const float* mlp_w1  = (const float*)d_in[10];
    const float* mlp_b1  = (const float*)d_in[11];
    const float* mlp_w2  = (const float*)d_in[12];
    const float* mlp_b2  = (const float*)d_in[13];
    const float* eln1_g  = (const float*)d_in[14];
    const float* eln1_b  = (const float*)d_in[15];
    const float* w_trans = (const float*)d_in[16];
    const float* b_trans = (const float*)d_in[17];
    const float* w0      = (const float*)d_in[18];
    const float* b0      = (const float*)d_in[19];
    const float* w1      = (const float*)d_in[20];
    const float* b1      = (const float*)d_in[21];
    const float* w_proj2 = (const float*)d_in[22];
    const float* b_proj2 = (const float*)d_in[23];
    const float* eln2_g  = (const float*)d_in[24];
    const float* eln2_b  = (const float*)d_in[25];
    const float* emlp_w1 = (const float*)d_in[26];
    const float* emlp_b1 = (const float*)d_in[27];
    const float* emlp_w2 = (const float*)d_in[28];
    const float* emlp_b2 = (const float*)d_in[29];
    float* out = (float*)d_out;

    float *px, *ph, *pqkv, *po, *pbig, *pa, *ps0, *ps1, *pmean;
    cudaGetSymbolAddress((void**)&px,    g_x);
    cudaGetSymbolAddress((void**)&ph,    g_h);
    cudaGetSymbolAddress((void**)&pqkv,  g_qkv);
    cudaGetSymbolAddress((void**)&po,    g_o);
    cudaGetSymbolAddress((void**)&pbig,  g_big);
    cudaGetSymbolAddress((void**)&pa,    g_a);
    cudaGetSymbolAddress((void**)&ps0,   g_s0);
    cudaGetSymbolAddress((void**)&ps1,   g_s1);
    cudaGetSymbolAddress((void**)&pmean, g_mean);

    const int attn_smem = ATTN_SMEM_FLOATS * (int)sizeof(float);
    cudaFuncSetAttribute(attn_fused, cudaFuncAttributeMaxDynamicSharedMemorySize, attn_smem);

    dim3 blk(256);
    const int MB = (RR + 127) / 128;   // 61
    const int NB_TD  = (TD  + 63) / 64;   // 26
    const int NB_DD  = (DD  + 63) / 64;   // 9
    const int NB_M1  = (M1  + 63) / 64;   // 34
    const int NB_UPD = (UPD + 63) / 64;   // 17

    // x -> g_x (running residual stream)
    copy_kernel<<<(RR * DD + 255) / 256, blk>>>(x, px, RR * DD);

    // --- block 1: attention ---
    ln_kernel<<<RR, blk>>>(px, ph, ln1_g, ln1_b);
    gemm_mma<0><<<dim3(NB_TD, MB), blk>>>(ph, w_qkv, nullptr, pqkv, RR, TD, DD);
    attn_fused<<<BSZ * HH, blk, attn_smem>>>(pqkv, b_table, po);
    gemm_mma<1><<<dim3(NB_DD, MB), blk>>>(po, w_proj, b_proj, px, RR, DD, DD);

    // --- block 2: MLP ---
    ln_kernel<<<RR, blk>>>(px, ph, ln2_g, ln2_b);
    gemm_mma<2><<<dim3(NB_M1, MB), blk>>>(ph, mlp_w1, mlp_b1, pbig, RR, M1, DD);
    gemm_mma<1><<<dim3(NB_DD, MB), blk>>>(pbig, mlp_w2, mlp_b2, px, RR, DD, M1);

    // --- block 3: seed attention ---
    ln_kernel<<<RR, blk>>>(px, ph, eln1_g, eln1_b);
    float* pxu = pbig;                       // RR x UPD
    float* po2 = pbig + (size_t)RR * UPD;    // RR x UPD
    gemm_mma<0><<<dim3(NB_UPD, MB), blk>>>(ph, w_trans, b_trans, pxu, RR, UPD, DD);
    gemm_mma<0><<<dim3(NB_UPD, 1), blk>>>(seed, w0, b0, ps0, NSD, UPD, DD);
    gemm_mma<0><<<dim3(NB_UPD, 1), blk>>>(seed, w1, b1, ps1, NSD, UPD, DD);
    seed_scores<<<BSZ * HH * NN, dim3(128)>>>(pxu, ps0, pa);
    softmax_f<<<BSZ * HH * NSD, blk>>>(pa);
    zero_mean<<<1, 32>>>(pmean);
    norm_n_mean<<<BSZ * HH, blk>>>(pa, pmean);
    seed_out<<<(RR * UPD + 255) / 256, blk>>>(pa, ps1, po2);
    gemm_mma<1><<<dim3(NB_DD, MB), blk>>>(po2, w_proj2, b_proj2, px, RR, DD, UPD);

    // --- block 4: expansion MLP ---
    ln_kernel<<<RR, blk>>>(px, ph, eln2_g, eln2_b);
    gemm_mma<2><<<dim3(NB_UPD, MB), blk>>>(ph, emlp_w1, emlp_b1, pbig, RR, UPD, DD);

    // write final residual directly into out: copy px, then accumulate last GEMM into out
    copy_kernel<<<(RR * DD + 255) / 256, blk>>>(px, out, RR * DD);
    gemm_mma<1><<<dim3(NB_DD, MB), blk>>>(pbig, emlp_w2, emlp_b2, out, RR, DD, UPD);

    finalize_mean<<<1, 32>>>(pmean, out);
}

// round 9
// speedup vs baseline: 2.5847x; 1.0346x over previous
#include <cuda_runtime.h>
#include <math.h>
#include <stdint.h>

// ---------------- problem constants ----------------
#define BSZ   32
#define NN    243
#define DD    544
#define HH    8
#define HDIM  68
#define NSD   17
#define UPD   1088          // UP*D
#define UCC   136           // UP*D/H
#define M1    2176          // 4*D
#define RR    (BSZ*NN)      // 7776
#define TD    (3*DD)        // 1632
#define BT    (2*NN-1)      // 485

// rounded-weight scratch offsets (floats)
#define OFF_QKV    0
#define OFF_PROJ   887808
#define OFF_MW1    1183744
#define OFF_MW2    2367488
#define OFF_TRANS  3551232
#define OFF_W0     4143104
#define OFF_W1     4734976
#define OFF_PROJ2  5326848
#define OFF_EW1    5918720
#define OFF_EW2    6510592
#define WTS_TOTAL  7102464

// ---------------- scratch (device globals; no allocs allowed) ----------------
__device__ float g_x[RR*DD];
__device__ float g_h[RR*DD];
__device__ float g_qkv[RR*TD];
__device__ float g_o[RR*DD];
__device__ float g_big[RR*M1];          // reused: mlp hidden | xu + o2 | emlp hidden
__device__ float g_a[BSZ*HH*NN*NSD];
__device__ float g_s0[NSD*UPD];
__device__ float g_s1[NSD*UPD];
__device__ float g_mean[NSD];
__device__ float g_wts[WTS_TOTAL];      // tf32-rounded weights
__device__ float g_seedr[NSD*DD];       // tf32-rounded seed

__device__ __forceinline__ float gelu_exact(float v) {
    return 0.5f * v * (1.0f + erff(v * 0.70710678118654752f));
}

__device__ __forceinline__ float to_tf32(float x) {
    unsigned r;
    asm("cvt.rna.tf32.f32 %0, %1;" : "=r"(r) : "f"(x));
    return __uint_as_float(r);
}

__device__ __forceinline__ void mma_tf32(float* c, const float* a, const float* b) {
    asm volatile(
        "mma.sync.aligned.m16n8k8.row.col.f32.tf32.tf32.f32 "
        "{%0,%1,%2,%3},{%4,%5,%6,%7},{%8,%9},{%0,%1,%2,%3};"
        : "+f"(c[0]), "+f"(c[1]), "+f"(c[2]), "+f"(c[3])
        : "r"(__float_as_uint(a[0])), "r"(__float_as_uint(a[1])),
          "r"(__float_as_uint(a[2])), "r"(__float_as_uint(a[3])),
          "r"(__float_as_uint(b[0])), "r"(__float_as_uint(b[1])));
}

__device__ __forceinline__ uint32_t smem_u32(const void* p) {
    return (uint32_t)__cvta_generic_to_shared(p);
}
__device__ __forceinline__ void cp_async16(uint32_t dst, const void* src, int srcsize) {
    asm volatile("cp.async.cg.shared.global [%0], [%1], 16, %2;"
                 :: "r"(dst), "l"(src), "r"(srcsize));
}
#define CP_COMMIT() asm volatile("cp.async.commit_group;" ::: "memory")
#define CP_WAIT1()  asm volatile("cp.async.wait_group 1;" ::: "memory")

// ---------------- generic copy / round ----------------
__global__ void copy_kernel(const float* __restrict__ in, float* __restrict__ out, int n) {
    int i = blockIdx.x * blockDim.x + threadIdx.x;
    if (i < n) out[i] = in[i];
}
__global__ void round_tf32_kernel(const float* __restrict__ in, float* __restrict__ out, int n) {
    int i = blockIdx.x * blockDim.x + threadIdx.x;
    if (i < n) out[i] = to_tf32(in[i]);
}

// ---------------- layernorm: one block per row, D=544; output tf32-rounded -----
__global__ void ln_kernel(const float* __restrict__ in, float* __restrict__ out,
                          const float* __restrict__ g, const float* __restrict__ b) {
    int row = blockIdx.x;
    const float* xr = in + (size_t)row * DD;
    __shared__ float red[256];
    int tid = threadIdx.x;

    float s = 0.f;
    for (int i = tid; i < DD; i += 256) s += xr[i];
    red[tid] = s; __syncthreads();
    for (int off = 128; off; off >>= 1) { if (tid < off) red[tid] += red[tid + off]; __syncthreads(); }
    float mean = red[0] * (1.0f / DD);
    __syncthreads();

    float s2 = 0.f;
    for (int i = tid; i < DD; i += 256) { float d = xr[i] - mean; s2 += d * d; }
    red[tid] = s2; __syncthreads();
    for (int off = 128; off; off >>= 1) { if (tid < off) red[tid] += red[tid + off]; __syncthreads(); }
    float rs = rsqrtf(red[0] * (1.0f / DD) + 1e-5f);

    for (int i = tid; i < DD; i += 256)
        out[(size_t)row * DD + i] = to_tf32((xr[i] - mean) * rs * g[i] + b[i]);
}

// ---------------- tf32 tensor-core NT GEMM v2 ----------------
// C[M,Nc] = A[M,K] @ B[Nc,K]^T (+bias)(epilogue)
// A and B must already be tf32-rounded (raw bits loaded via cp.async).
// EPI: 0 = store fp32, 1 = accumulate (residual), 2 = gelu store (tf32-rounded)
// CTA tile 128x128, BK=16, 8 warps in 2(M) x 4(N); warp tile 64x32 = 4x4 m16n8k8.
// Double-buffered SMEM with cp.async. K % 16 == 0; M, Nc guarded.
#define PAD 20
template <int EPI>
__global__ __launch_bounds__(256, 2)
void gemm_mma(const float* __restrict__ A, const float* __restrict__ B,
              const float* __restrict__ bias, float* __restrict__ C,
              int M, int Nc, int K) {
    __shared__ __align__(16) float As[2][128][PAD];
    __shared__ __align__(16) float Bs[2][128][PAD];

    int tid  = threadIdx.x;
    int lane = tid & 31;
    int warp = tid >> 5;
    int wm   = warp >> 2;      // 0..1 -> 64-row slab
    int wn   = warp & 3;       // 0..3 -> 32-col slab

    int row0 = blockIdx.y * 128;
    int col0 = blockIdx.x * 128;

    int g = lane >> 2;         // 0..7
    int t = lane & 3;          // 0..3

    int lr = tid >> 2;         // 0..63
    int lc = (tid & 3) * 4;    // 0,4,8,12

    int ra0 = row0 + lr, ra1 = row0 + lr + 64;
    int rb0 = col0 + lr, rb1 = col0 + lr + 64;
    const float* pa0 = A + (size_t)(ra0 < M ? ra0 : 0) * K + lc;
    const float* pa1 = A + (size_t)(ra1 < M ? ra1 : 0) * K + lc;
    const float* pb0 = B + (size_t)(rb0 < Nc ? rb0 : 0) * K + lc;
    const float* pb1 = B + (size_t)(rb1 < Nc ? rb1 : 0) * K + lc;
    int sa0 = (ra0 < M) ? 16 : 0, sa1 = (ra1 < M) ? 16 : 0;
    int sb0 = (rb0 < Nc) ? 16 : 0, sb1 = (rb1 < Nc) ? 16 : 0;

    uint32_t dA0 = smem_u32(&As[0][lr][lc]);
    uint32_t dA1 = smem_u32(&As[0][lr + 64][lc]);
    uint32_t dB0 = smem_u32(&Bs[0][lr][lc]);
    uint32_t dB1 = smem_u32(&Bs[0][lr + 64][lc]);
    const uint32_t bufStrideA = (uint32_t)(128 * PAD * 4);
    const uint32_t bufStrideB = (uint32_t)(128 * PAD * 4);

    float acc[4][4][4];
    #pragma unroll
    for (int mi = 0; mi < 4; mi++)
        #pragma unroll
        for (int ni = 0; ni < 4; ni++)
            #pragma unroll
            for (int q = 0; q < 4; q++) acc[mi][ni][q] = 0.f;

    int nkt = K >> 4;

    // prologue: tile 0 -> buffer 0
    cp_async16(dA0, pa0, sa0);
    cp_async16(dA1, pa1, sa1);
    cp_async16(dB0, pb0, sb0);
    cp_async16(dB1, pb1, sb1);
    CP_COMMIT();

    for (int kt = 0; kt < nkt; ++kt) {
        int cur = kt & 1, nxt = cur ^ 1;
        if (kt + 1 < nkt) {
            int k0 = (kt + 1) << 4;
            cp_async16(dA0 + nxt * bufStrideA, pa0 + k0, sa0);
            cp_async16(dA1 + nxt * bufStrideA, pa1 + k0, sa1);
            cp_async16(dB0 + nxt * bufStrideB, pb0 + k0, sb0);
            cp_async16(dB1 + nxt * bufStrideB, pb1 + k0, sb1);
        }
        CP_COMMIT();
        CP_WAIT1();            // tile kt resident
        __syncthreads();

        #pragma unroll
        for (int kk = 0; kk < 16; kk += 8) {
            float afr[4][4], bfr[4][2];
            #pragma unroll
            for (int mi = 0; mi < 4; mi++) {
                int mb = wm * 64 + mi * 16;
                afr[mi][0] = As[cur][mb + g     ][kk + t    ];
                afr[mi][1] = As[cur][mb + g + 8 ][kk + t    ];
                afr[mi][2] = As[cur][mb + g     ][kk + t + 4];
                afr[mi][3] = As[cur][mb + g + 8 ][kk + t + 4];
            }
            #pragma unroll
            for (int ni = 0; ni < 4; ni++) {
                int nb = wn * 32 + ni * 8;
                bfr[ni][0] = Bs[cur][nb + g][kk + t    ];
                bfr[ni][1] = Bs[cur][nb + g][kk + t + 4];
            }
            #pragma unroll
            for (int mi = 0; mi < 4; mi++)
                #pragma unroll
                for (int ni = 0; ni < 4; ni++)
                    mma_tf32(acc[mi][ni], afr[mi], bfr[ni]);
        }
        __syncthreads();       // protect buffer 'nxt' before next iteration's cp.async
    }

    // epilogue: c0:(g,2t) c1:(g,2t+1) c2:(g+8,2t) c3:(g+8,2t+1)
    #pragma unroll
    for (int mi = 0; mi < 4; mi++) {
        #pragma unroll
        for (int rh = 0; rh < 2; rh++) {
            int r = row0 + wm * 64 + mi * 16 + g + rh * 8;
            if (r >= M) continue;
            #pragma unroll
            for (int ni = 0; ni < 4; ni++) {
                int c = col0 + wn * 32 + ni * 8 + t * 2;
                if (c >= Nc) continue;   // Nc even, c even -> c+1 < Nc too
                #pragma unroll
                for (int cc = 0; cc < 2; cc++) {
                    float v = acc[mi][ni][rh * 2 + cc];
                    if (bias) v += bias[c + cc];
                    size_t idx = (size_t)r * Nc + c + cc;
                    if (EPI == 1)      C[idx] += v;
                    else if (EPI == 2) C[idx] = to_tf32(gelu_exact(v));
                    else               C[idx] = v;
                }
            }
        }
    }
}

// ---------------- fused attention: one block per (b,h); K,V resident in SMEM ----
#define ATTN_SMEM_FLOATS (2*NN*69 + NN + 256 + 3*HDIM + HDIM)
__global__ void attn_fused(const float* __restrict__ qkv, const float* __restrict__ btab,
                           float* __restrict__ o) {
    extern __shared__ float sm[];
    float* sK  = sm;
    float* sV  = sK + NN * 69;
    float* sS  = sV + NN * 69;
    float* red = sS + NN;
    float* sO  = red + 256;
    float* sQ  = sO + 3 * HDIM;

    int b = blockIdx.x / HH, h = blockIdx.x % HH;
    int tid = threadIdx.x;
    const float* base = qkv + (size_t)b * NN * TD + h * HDIM;

    for (int idx = tid; idx < NN * HDIM; idx += 256) {
        int j = idx / HDIM, d = idx - j * HDIM;
        sK[j * 69 + d] = base[(size_t)j * TD + DD + d];
        sV[j * 69 + d] = base[(size_t)j * TD + 2 * DD + d];
    }
    const float scale = rsqrtf((float)HDIM);
    const float* bt = btab + h * BT;

    for (int i = 0; i < NN; ++i) {
        __syncthreads();
        if (tid < HDIM) sQ[tid] = base[(size_t)i * TD + tid];
        __syncthreads();

        float lmax = -1e30f;
        if (tid < NN) {
            float s = 0.f;
            #pragma unroll 4
            for (int d = 0; d < HDIM; ++d) s = fmaf(sQ[d], sK[tid * 69 + d], s);
            s = s * scale + bt[i - tid + NN - 1];
            sS[tid] = s;
            lmax = s;
        }
        red[tid] = lmax; __syncthreads();
        for (int off = 128; off; off >>= 1) { if (tid < off) red[tid] = fmaxf(red[tid], red[tid + off]); __syncthreads(); }
        float mx = red[0]; __syncthreads();

        float e = 0.f;
        if (tid < NN) { e = __expf(sS[tid] - mx); sS[tid] = e; }
        red[tid] = e; __syncthreads();
        for (int off = 128; off; off >>= 1) { if (tid < off) red[tid] += red[tid + off]; __syncthreads(); }
        float inv = 1.f / red[0];
        __syncthreads();

        int chunk = tid / HDIM;
        if (chunk < 3) {
            int d = tid - chunk * HDIM;
            int j0 = chunk * 81, j1 = j0 + 81;
            if (j1 > NN) j1 = NN;
            float acc = 0.f;
            for (int j = j0; j < j1; ++j) acc = fmaf(sS[j], sV[j * 69 + d], acc);
            sO[chunk * HDIM + d] = acc;
        }
        __syncthreads();
        if (tid < HDIM)
            o[(size_t)(b * NN + i) * DD + h * HDIM + tid] =
                to_tf32((sO[tid] + sO[HDIM + tid] + sO[2 * HDIM + tid]) * inv);
    }
}

// ---------------- seed attention ----------------
__global__ void seed_scores(const float* __restrict__ xu, const float* __restrict__ s0,
                            float* __restrict__ a) {
    int bid = blockIdx.x;
    int f = bid % NN;
    int t = bid / NN;
    int h = t % HH, b = t / HH;
    __shared__ float sx[UCC];
    const float* xr = xu + (size_t)(b * NN + f) * UPD + h * UCC;
    for (int i = threadIdx.x; i < UCC; i += blockDim.x) sx[i] = xr[i];
    __syncthreads();
    if (threadIdx.x < NSD) {
        const float* sr = s0 + (size_t)threadIdx.x * UPD + h * UCC;
        float acc = 0.f;
        #pragma unroll 4
        for (int c = 0; c < UCC; ++c) acc = fmaf(sx[c], sr[c], acc);
        a[((size_t)(b * HH + h) * NN + f) * NSD + threadIdx.x] = acc;
    }
}

__global__ void softmax_f(float* __restrict__ a) {
    int bid = blockIdx.x;
    int n = bid % NSD, bh = bid / NSD;
    __shared__ float red[256];
    int f = threadIdx.x;
    size_t base = (size_t)bh * NN * NSD + n;
    float v = (f < NN) ? a[base + (size_t)f * NSD] : -1e30f;
    red[f] = v; __syncthreads();
    for (int off = 128; off; off >>= 1) { if (f < off) red[f] = fmaxf(red[f], red[f + off]); __syncthreads(); }
    float mx = red[0]; __syncthreads();
    float e = (f < NN) ? __expf(v - mx) : 0.f;
    red[f] = e; __syncthreads();
    for (int off = 128; off; off >>= 1) { if (f < off) red[f] += red[f + off]; __syncthreads(); }
    float inv = 1.f / red[0];
    if (f < NN) a[base + (size_t)f * NSD] = e * inv;
}

__global__ void zero_mean(float* __restrict__ mean) {
    if (threadIdx.x < NSD) mean[threadIdx.x] = 0.f;
}

__global__ void norm_n_mean(float* __restrict__ a, float* __restrict__ mean) {
    int bh = blockIdx.x;  // 0..255
    __shared__ float sacc[NSD];
    if (threadIdx.x < NSD) sacc[threadIdx.x] = 0.f;
    __syncthreads();
    for (int f = threadIdx.x; f < NN; f += blockDim.x) {
        float* row = a + ((size_t)bh * NN + f) * NSD;
        float vals[NSD];
        float s = 0.f;
        #pragma unroll
        for (int n = 0; n < NSD; ++n) { vals[n] = row[n]; s += vals[n]; }
        float inv = 1.f / (1e-7f + s);
        #pragma unroll
        for (int n = 0; n < NSD; ++n) {
            float nv = vals[n] * inv;
            row[n] = nv;
            atomicAdd(&sacc[n], nv);
        }
    }
    __syncthreads();
    if (threadIdx.x < NSD) atomicAdd(&mean[threadIdx.x], sacc[threadIdx.x]);
}

__global__ void seed_out(const float* __restrict__ a, const float* __restrict__ s1,
                         float* __restrict__ o2) {
    int idx = blockIdx.x * blockDim.x + threadIdx.x;
    if (idx >= RR * UPD) return;
    int r = idx / UPD, c = idx - r * UPD;
    int b = r / NN, f = r - b * NN;
    int h = c / UCC;
    const float* ar = a + ((size_t)(b * HH + h) * NN + f) * NSD;
    float acc = 0.f;
    #pragma unroll
    for (int n = 0; n < NSD; ++n) acc = fmaf(ar[n], s1[(size_t)n * UPD + c], acc);
    o2[idx] = to_tf32(acc);
}

__global__ void finalize_mean(const float* __restrict__ mean, float* __restrict__ out) {
    if (threadIdx.x < NSD)
        out[(size_t)RR * DD + threadIdx.x] = mean[threadIdx.x] * (1.0f / (BSZ * HH * NN));
}

// ---------------- launch ----------------
extern "C" void kernel_launch(void* const* d_in, const int* in_sizes, int n_in,
                              void* d_out, int out_size) {
    (void)in_sizes; (void)n_in; (void)out_size;
    const float* x       = (const float*)d_in[0];
    const float* seed    = (const float*)d_in[1];
    const float* ln1_g   = (const float*)d_in[2];
    const float* ln1_b   = (const float*)d_in[3];
    const float* w_qkv   = (const float*)d_in[4];
    const float* w_proj  = (const float*)d_in[5];
    const float* b_proj  = (const float*)d_in[6];
    const float* b_table = (const float*)d_in[7];
    const float* ln2_g   = (const float*)d_in[8];
    const float* ln2_b   = (const float*)d_in[9];
    const float* mlp_w1  = (const float*)d_in[10];
    const float* mlp_b1  = (const float*)d_in[11];
    const float* mlp_w2  = (const float*)d_in[12];
    const float* mlp_b2  = (const float*)d_in[13];
    const float* eln1_g  = (const float*)d_in[14];
    const float* eln1_b  = (const float*)d_in[15];
    const float* w_trans = (const float*)d_in[16];
    const float* b_trans = (const float*)d_in[17];
    const float* w0      = (const float*)d_in[18];
    const float* b0      = (const float*)d_in[19];
    const float* w1      = (const float*)d_in[20];
    const float* b1      = (const float*)d_in[21];
    const float* w_proj2 = (const float*)d_in[22];
    const float* b_proj2 = (const float*)d_in[23];
    const float* eln2_g  = (const float*)d_in[24];
    const float* eln2_b  = (const float*)d_in[25];
    const float* emlp_w1 = (const float*)d_in[26];
    const float* emlp_b1 = (const float*)d_in[27];
    const float* emlp_w2 = (const float*)d_in[28];
    const float* emlp_b2 = (const float*)d_in[29];
    float* out = (float*)d_out;

    float *px, *ph, *pqkv, *po, *pbig, *pa, *ps0, *ps1, *pmean, *pw, *psr;
    cudaGetSymbolAddress((void**)&px,    g_x);
    cudaGetSymbolAddress((void**)&ph,    g_h);
    cudaGetSymbolAddress((void**)&pqkv,  g_qkv);
    cudaGetSymbolAddress((void**)&po,    g_o);
    cudaGetSymbolAddress((void**)&pbig,  g_big);
    cudaGetSymbolAddress((void**)&pa,    g_a);
    cudaGetSymbolAddress((void**)&ps0,   g_s0);
    cudaGetSymbolAddress((void**)&ps1,   g_s1);
    cudaGetSymbolAddress((void**)&pmean, g_mean);
    cudaGetSymbolAddress((void**)&pw,    g_wts);
    cudaGetSymbolAddress((void**)&psr,   g_seedr);

    const int attn_smem = ATTN_SMEM_FLOATS * (int)sizeof(float);
    cudaFuncSetAttribute(attn_fused, cudaFuncAttributeMaxDynamicSharedMemorySize, attn_smem);

    dim3 blk(256);
    const int MB = (RR + 127) / 128;        // 61
    const int NB_TD  = (TD  + 127) / 128;   // 13
    const int NB_DD  = (DD  + 127) / 128;   // 5
    const int NB_M1  = (M1  + 127) / 128;   // 17
    const int NB_UPD = (UPD + 127) / 128;   // 9

    // ---- pre-round all GEMM B operands (weights) + seed into tf32 scratch ----
    #define RND(src, off, n) round_tf32_kernel<<<((n) + 255) / 256, blk>>>(src, pw + (off), n)
    RND(w_qkv,   OFF_QKV,   TD * DD);
    RND(w_proj,  OFF_PROJ,  DD * DD);
    RND(mlp_w1,  OFF_MW1,   M1 * DD);
    RND(mlp_w2,  OFF_MW2,   DD * M1);
    RND(w_trans, OFF_TRANS, UPD * DD);
    RND(w0,      OFF_W0,    UPD * DD);
    RND(w1,      OFF_W1,    UPD * DD);
    RND(w_proj2, OFF_PROJ2, DD * UPD);
    RND(emlp_w1, OFF_EW1,   UPD * DD);
    RND(emlp_w2, OFF_EW2,   DD * UPD);
    #undef RND
    round_tf32_kernel<<<(NSD * DD + 255) / 256, blk>>>(seed, psr, NSD * DD);

    // x -> g_x (running residual stream)
    copy_kernel<<<(RR * DD + 255) / 256, blk>>>(x, px, RR * DD);

    // --- block 1: attention ---
    ln_kernel<<<RR, blk>>>(px, ph, ln1_g, ln1_b);
    gemm_mma<0><<<dim3(NB_TD, MB), blk>>>(ph, pw + OFF_QKV, nullptr, pqkv, RR, TD, DD);
    attn_fused<<<BSZ * HH, blk, attn_smem>>>(pqkv, b_table, po);
    gemm_mma<1><<<dim3(NB_DD, MB), blk>>>(po, pw + OFF_PROJ, b_proj, px, RR, DD, DD);

    // --- block 2: MLP ---
    ln_kernel<<<RR, blk>>>(px, ph, ln2_g, ln2_b);
    gemm_mma<2><<<dim3(NB_M1, MB), blk>>>(ph, pw + OFF_MW1, mlp_b1, pbig, RR, M1, DD);
    gemm_mma<1><<<dim3(NB_DD, MB), blk>>>(pbig, pw + OFF_MW2, mlp_b2, px, RR, DD, M1);

    // --- block 3: seed attention ---
    ln_kernel<<<RR, blk>>>(px, ph, eln1_g, eln1_b);
    float* pxu = pbig;                       // RR x UPD
    float* po2 = pbig + (size_t)RR * UPD;    // RR x UPD
    gemm_mma<0><<<dim3(NB_UPD, MB), blk>>>(ph, pw + OFF_TRANS, b_trans, pxu, RR, UPD, DD);
    gemm_mma<0><<<dim3(NB_UPD, 1), blk>>>(psr, pw + OFF_W0, b0, ps0, NSD, UPD, DD);
    gemm_mma<0><<<dim3(NB_UPD, 1), blk>>>(psr, pw + OFF_W1, b1, ps1, NSD, UPD, DD);
    seed_scores<<<BSZ * HH * NN, dim3(128)>>>(pxu, ps0, pa);
    softmax_f<<<BSZ * HH * NSD, blk>>>(pa);
    zero_mean<<<1, 32>>>(pmean);
    norm_n_mean<<<BSZ * HH, blk>>>(pa, pmean);
    seed_out<<<(RR * UPD + 255) / 256, blk>>>(pa, ps1, po2);
    gemm_mma<1><<<dim3(NB_DD, MB), blk>>>(po2, pw + OFF_PROJ2, b_proj2, px, RR, DD, UPD);

    // --- block 4: expansion MLP ---
    ln_kernel<<<RR, blk>>>(px, ph, eln2_g, eln2_b);
    gemm_mma<2><<<dim3(NB_UPD, MB), blk>>>(ph, pw + OFF_EW1, emlp_b1, pbig, RR, UPD, DD);

    // write final residual directly into out: copy px, then accumulate last GEMM into out
    copy_kernel<<<(RR * DD + 255) / 256, blk>>>(px, out, RR * DD);
    gemm_mma<1><<<dim3(NB_DD, MB), blk>>>(pbig, pw + OFF_EW2, emlp_b2, out, RR, DD, UPD);

    finalize_mean<<<1, 32>>>(pmean, out);
}